// round 1
// baseline (speedup 1.0000x reference)
#include <cuda_runtime.h>
#include <math.h>

#define NN 8192
#define HH 1024
#define NSTEPS 8

// ---------------- persistent device state (no allocs allowed) ----------------
__device__ float g_attn_feat[NN * HH];   // enc @ attn_wm
__device__ float g_hop_feat[NN * HH];    // enc @ hop_wm
__device__ float g_hbuf[2][2][HH];       // [parity][chain]
__device__ float g_cbuf[2][2][HH];
__device__ float g_x[2][HH];             // LSTM input per chain
__device__ float g_q[2][HH];             // glimpse context
__device__ float g_hq[2][HH];            // h @ hop_wq
__device__ float g_aq[2][HH];            // q @ attn_wq
__device__ float g_sel[NN];
__device__ float g_neg[NN];
__device__ float g_w[2][NN];             // softmax weights exp(s)
__device__ float g_part[2][64][HH];      // weighted-sum partials
__device__ float g_amax_val[NN / 8];
__device__ int   g_amax_idx[NN / 8];

__device__ __forceinline__ float fast_tanh(float x) {
    x = fminf(15.0f, fmaxf(-15.0f, x));
    float e = __expf(2.0f * x);
    return __fdividef(e - 1.0f, e + 1.0f);
}
__device__ __forceinline__ float sigmoidf_(float x) { return 1.0f / (1.0f + expf(-x)); }

// ---------------- init ----------------
__global__ void init_kernel(const int* __restrict__ mask, const float* __restrict__ init_i,
                            const float* __restrict__ init_h, const float* __restrict__ init_c) {
    int i = blockIdx.x * 256 + threadIdx.x;
    if (i < NN) {
        g_sel[i] = 0.0f;
        g_neg[i] = (mask[i] == 0) ? -1e8f : 0.0f;
    }
    if (i < HH) {
        g_x[0][i] = init_i[i];      g_x[1][i] = init_i[i];
        g_hbuf[0][0][i] = init_h[i]; g_hbuf[0][1][i] = init_h[i];
        g_cbuf[0][0][i] = init_c[i]; g_cbuf[0][1][i] = init_c[i];
    }
}

// ---------------- big GEMM: C[n,h] = sum_k A[n,k] * B[k,h] ----------------
// 128x128 tile, BK=8, 256 threads, 8x8 per thread. blockIdx.z picks (attn|hop).
__global__ void __launch_bounds__(256) gemm_kernel(const float* __restrict__ A,
                                                   const float* __restrict__ B0,
                                                   const float* __restrict__ B1) {
    const float* B = (blockIdx.z == 0) ? B0 : B1;
    float* C = (blockIdx.z == 0) ? g_attn_feat : g_hop_feat;
    __shared__ float As[8][128];
    __shared__ float Bs[8][128];
    const int tid = threadIdx.x;
    const int row0 = blockIdx.y * 128, col0 = blockIdx.x * 128;
    const int aRow = tid >> 1, aCol = (tid & 1) * 4;
    const int bRow = tid >> 5, bCol = (tid & 31) * 4;
    const int ty = tid >> 4, tx = tid & 15;
    const int K = HH, NC = HH;

    float acc[8][8];
#pragma unroll
    for (int i = 0; i < 8; i++)
#pragma unroll
        for (int j = 0; j < 8; j++) acc[i][j] = 0.0f;

    for (int k0 = 0; k0 < K; k0 += 8) {
        float4 a = *(const float4*)&A[(size_t)(row0 + aRow) * K + k0 + aCol];
        As[aCol + 0][aRow] = a.x; As[aCol + 1][aRow] = a.y;
        As[aCol + 2][aRow] = a.z; As[aCol + 3][aRow] = a.w;
        *(float4*)&Bs[bRow][bCol] = *(const float4*)&B[(size_t)(k0 + bRow) * NC + col0 + bCol];
        __syncthreads();
#pragma unroll
        for (int kk = 0; kk < 8; kk++) {
            float ar[8], br[8];
            *(float4*)(ar)     = *(float4*)&As[kk][ty * 8];
            *(float4*)(ar + 4) = *(float4*)&As[kk][ty * 8 + 4];
            *(float4*)(br)     = *(float4*)&Bs[kk][tx * 8];
            *(float4*)(br + 4) = *(float4*)&Bs[kk][tx * 8 + 4];
#pragma unroll
            for (int i = 0; i < 8; i++)
#pragma unroll
                for (int j = 0; j < 8; j++) acc[i][j] += ar[i] * br[j];
        }
        __syncthreads();
    }
#pragma unroll
    for (int i = 0; i < 8; i++) {
        float* cp = &C[(size_t)(row0 + ty * 8 + i) * NC + col0 + tx * 8];
        float4 v0 = make_float4(acc[i][0], acc[i][1], acc[i][2], acc[i][3]);
        float4 v1 = make_float4(acc[i][4], acc[i][5], acc[i][6], acc[i][7]);
        *(float4*)cp = v0; *(float4*)(cp + 4) = v1;
    }
}

// ---------------- LSTM step (both chains; h/c ping-pong on parity) ----------------
__global__ void lstm_kernel(const float* __restrict__ w_ih, const float* __restrict__ w_hh,
                            const float* __restrict__ b_ih, const float* __restrict__ b_hh,
                            int parity) {
    const int chain = blockIdx.y;
    __shared__ float xs[HH], hs[HH];
    for (int i = threadIdx.x; i < HH; i += 256) {
        xs[i] = g_x[chain][i];
        hs[i] = g_hbuf[parity][chain][i];
    }
    __syncthreads();
    const int warp = threadIdx.x >> 5, lane = threadIdx.x & 31;
    const int j = blockIdx.x * 8 + warp;    // 128 blocks * 8 warps = 1024
    float acc[4];
#pragma unroll
    for (int g = 0; g < 4; g++) {
        const float* wi = w_ih + (size_t)(g * HH + j) * HH;
        const float* wh = w_hh + (size_t)(g * HH + j) * HH;
        float a = 0.0f;
        for (int k = lane; k < HH; k += 32) a += xs[k] * wi[k] + hs[k] * wh[k];
        acc[g] = a;
    }
#pragma unroll
    for (int o = 16; o; o >>= 1)
#pragma unroll
        for (int g = 0; g < 4; g++) acc[g] += __shfl_xor_sync(0xffffffffu, acc[g], o);
    if (lane == 0) {
        float gi = sigmoidf_(acc[0] + b_ih[j] + b_hh[j]);
        float gf = sigmoidf_(acc[1] + b_ih[HH + j] + b_hh[HH + j]);
        float gg = tanhf(acc[2] + b_ih[2 * HH + j] + b_hh[2 * HH + j]);
        float go = sigmoidf_(acc[3] + b_ih[3 * HH + j] + b_hh[3 * HH + j]);
        float cn = gf * g_cbuf[parity][chain][j] + gi * gg;
        g_cbuf[parity ^ 1][chain][j] = cn;
        g_hbuf[parity ^ 1][chain][j] = go * tanhf(cn);
    }
}

// ---------------- query projection: out[h] = sum_k v[k] * W[k,h] ----------------
__global__ void proj_kernel(const float* __restrict__ W, int mode, int parity) {
    const int chain = blockIdx.y;
    const float* v = (mode == 0) ? g_hbuf[parity ^ 1][chain] : g_q[chain];
    float* o = (mode == 0) ? g_hq[chain] : g_aq[chain];
    __shared__ float vs[HH];
    for (int i = threadIdx.x; i < HH; i += 256) vs[i] = v[i];
    __syncthreads();
    const int col = blockIdx.x * 256 + threadIdx.x;
    float acc = 0.0f;
#pragma unroll 8
    for (int k = 0; k < HH; k++) acc += vs[k] * W[(size_t)k * HH + col];
    o[col] = acc;
}

// ---------------- glimpse scores -> softmax weights (both chains) ----------------
__global__ void hop_score_kernel(const float* __restrict__ hop_v) {
    const int chain = blockIdx.y;
    __shared__ float qs[HH], vs[HH];
    for (int i = threadIdx.x; i < HH; i += 256) { qs[i] = g_hq[chain][i]; vs[i] = hop_v[i]; }
    __syncthreads();
    const int warp = threadIdx.x >> 5, lane = threadIdx.x & 31;
    const int n = blockIdx.x * 8 + warp;
    const float4* row = (const float4*)&g_hop_feat[(size_t)n * HH];
    float acc = 0.0f;
#pragma unroll
    for (int it = 0; it < 8; it++) {
        int k4 = lane + it * 32, k = k4 * 4;
        float4 f = row[k4];
        acc += fast_tanh(f.x + qs[k]) * vs[k] + fast_tanh(f.y + qs[k + 1]) * vs[k + 1]
             + fast_tanh(f.z + qs[k + 2]) * vs[k + 2] + fast_tanh(f.w + qs[k + 3]) * vs[k + 3];
    }
#pragma unroll
    for (int o = 16; o; o >>= 1) acc += __shfl_xor_sync(0xffffffffu, acc, o);
    if (lane == 0) g_w[chain][n] = expf(acc + g_neg[n]);
}

// ---------------- weighted sum partials: part[b][h] = sum_n w[n]*feat[n,h] ----------------
__global__ void wsum_kernel(const float* __restrict__ enc, int featsel) {
    const int chain = featsel ? 1 : blockIdx.y;
    const float* feat = featsel ? enc : g_hop_feat;
    const float* w = g_w[chain];
    const int c = threadIdx.x * 4;
    const int n0 = blockIdx.x * (NN / 64);
    float a0 = 0, a1 = 0, a2 = 0, a3 = 0;
#pragma unroll 4
    for (int n = n0; n < n0 + NN / 64; n++) {
        float wn = w[n];
        float4 f = *(const float4*)&feat[(size_t)n * HH + c];
        a0 += wn * f.x; a1 += wn * f.y; a2 += wn * f.z; a3 += wn * f.w;
    }
    *(float4*)&g_part[chain][blockIdx.x][c] = make_float4(a0, a1, a2, a3);
}

// ---------------- reduce partials -> q; actor writes states output ----------------
__global__ void hred_kernel(float* __restrict__ out, int step) {
    const int chain = blockIdx.y;
    const int col = blockIdx.x * 256 + threadIdx.x;
    float s = 0.0f;
#pragma unroll
    for (int b = 0; b < 64; b++) s += g_part[chain][b][col];
    float sw = 0.0f;
    for (int i = threadIdx.x; i < NN; i += 256) sw += g_w[chain][i];
#pragma unroll
    for (int o = 16; o; o >>= 1) sw += __shfl_xor_sync(0xffffffffu, sw, o);
    __shared__ float red[8];
    if ((threadIdx.x & 31) == 0) red[threadIdx.x >> 5] = sw;
    __syncthreads();
    float tot = 0.0f;
#pragma unroll
    for (int w = 0; w < 8; w++) tot += red[w];
    float q = s / tot;
    g_q[chain][col] = q;
    if (chain == 0) out[NSTEPS + step * HH + col] = q;
}

// ---------------- attn scores: actor -> argmax partials, critic -> weights ----------------
__global__ void attn_score_kernel(const float* __restrict__ attn_v) {
    const int chain = blockIdx.y;
    __shared__ float qs[HH], vs[HH];
    __shared__ float sv[8]; __shared__ int si[8];
    for (int i = threadIdx.x; i < HH; i += 256) { qs[i] = g_aq[chain][i]; vs[i] = attn_v[i]; }
    __syncthreads();
    const int warp = threadIdx.x >> 5, lane = threadIdx.x & 31;
    const int n = blockIdx.x * 8 + warp;
    const float4* row = (const float4*)&g_attn_feat[(size_t)n * HH];
    float acc = 0.0f;
#pragma unroll
    for (int it = 0; it < 8; it++) {
        int k4 = lane + it * 32, k = k4 * 4;
        float4 f = row[k4];
        acc += fast_tanh(f.x + qs[k]) * vs[k] + fast_tanh(f.y + qs[k + 1]) * vs[k + 1]
             + fast_tanh(f.z + qs[k + 2]) * vs[k + 2] + fast_tanh(f.w + qs[k + 3]) * vs[k + 3];
    }
#pragma unroll
    for (int o = 16; o; o >>= 1) acc += __shfl_xor_sync(0xffffffffu, acc, o);
    if (chain == 0) {
        if (lane == 0) { sv[warp] = acc + g_neg[n] + g_sel[n]; si[warp] = n; }
        __syncthreads();
        if (threadIdx.x == 0) {
            float bv = sv[0]; int bi = si[0];
#pragma unroll
            for (int w = 1; w < 8; w++)
                if (sv[w] > bv) { bv = sv[w]; bi = si[w]; }
            g_amax_val[blockIdx.x] = bv; g_amax_idx[blockIdx.x] = bi;
        }
    } else {
        if (lane == 0) g_w[1][n] = expf(acc + g_neg[n]);
    }
}

// ---------------- actor finalize: global argmax, sel update, next input, idx out ----------------
__global__ void actor_fin_kernel(const float* __restrict__ enc, float* __restrict__ out, int step) {
    __shared__ float bv[256]; __shared__ int bi[256];
    const int tid = threadIdx.x;
    float v = -3.4e38f; int id = 0;
    for (int b = tid; b < NN / 8; b += 256) {
        float pv = g_amax_val[b]; int pi = g_amax_idx[b];
        if (pv > v || (pv == v && pi < id)) { v = pv; id = pi; }
    }
    bv[tid] = v; bi[tid] = id;
    __syncthreads();
    for (int s = 128; s > 0; s >>= 1) {
        if (tid < s) {
            if (bv[tid + s] > bv[tid] || (bv[tid + s] == bv[tid] && bi[tid + s] < bi[tid])) {
                bv[tid] = bv[tid + s]; bi[tid] = bi[tid + s];
            }
        }
        __syncthreads();
    }
    __shared__ int chosen;
    if (tid == 0) {
        chosen = bi[0];
        g_sel[bi[0]] = -1e18f;
        out[step] = (float)bi[0];
    }
    __syncthreads();
    const int idx = chosen;
    for (int i = tid; i < HH; i += 256) g_x[0][i] = enc[(size_t)idx * HH + i];
}

// ---------------- critic reduce: ctx, score output, next input ----------------
__global__ void cred_kernel(const float* __restrict__ score_w, const float* __restrict__ score_b,
                            float* __restrict__ out, int step) {
    const int col = threadIdx.x;   // 1024 threads
    float s = 0.0f;
#pragma unroll
    for (int b = 0; b < 64; b++) s += g_part[1][b][col];
    float sw = 0.0f;
    for (int i = col; i < NN; i += 1024) sw += g_w[1][i];
#pragma unroll
    for (int o = 16; o; o >>= 1) sw += __shfl_xor_sync(0xffffffffu, sw, o);
    __shared__ float red[32];
    if ((col & 31) == 0) red[col >> 5] = sw;
    __syncthreads();
    float tot = 0.0f;
#pragma unroll
    for (int w = 0; w < 32; w++) tot += red[w];
    float ctx = s / tot;
    g_x[1][col] = ctx;
    float t = ctx * score_w[col];
#pragma unroll
    for (int o = 16; o; o >>= 1) t += __shfl_xor_sync(0xffffffffu, t, o);
    __shared__ float red2[32];
    if ((col & 31) == 0) red2[col >> 5] = t;
    __syncthreads();
    if (col == 0) {
        float stot = 0.0f;
#pragma unroll
        for (int w = 0; w < 32; w++) stot += red2[w];
        out[NSTEPS + NSTEPS * HH + step] = stot + score_b[0];
    }
}

// ---------------- launch ----------------
extern "C" void kernel_launch(void* const* d_in, const int* in_sizes, int n_in,
                              void* d_out, int out_size) {
    const float* enc     = (const float*)d_in[0];
    const int*   mask    = (const int*)d_in[1];
    const float* attn_wm = (const float*)d_in[2];
    const float* attn_wq = (const float*)d_in[3];
    const float* attn_v  = (const float*)d_in[4];
    const float* hop_wm  = (const float*)d_in[5];
    const float* hop_wq  = (const float*)d_in[6];
    const float* hop_v   = (const float*)d_in[7];
    const float* init_i  = (const float*)d_in[8];
    const float* init_h  = (const float*)d_in[9];
    const float* init_c  = (const float*)d_in[10];
    const float* w_ih    = (const float*)d_in[11];
    const float* w_hh    = (const float*)d_in[12];
    const float* b_ih    = (const float*)d_in[13];
    const float* b_hh    = (const float*)d_in[14];
    const float* score_w = (const float*)d_in[15];
    const float* score_b = (const float*)d_in[16];
    float* out = (float*)d_out;

    init_kernel<<<32, 256>>>(mask, init_i, init_h, init_c);
    gemm_kernel<<<dim3(8, 64, 2), 256>>>(enc, attn_wm, hop_wm);

    for (int t = 0; t < NSTEPS; t++) {
        const int p = t & 1;
        lstm_kernel<<<dim3(128, 2), 256>>>(w_ih, w_hh, b_ih, b_hh, p);
        proj_kernel<<<dim3(4, 2), 256>>>(hop_wq, 0, p);
        hop_score_kernel<<<dim3(NN / 8, 2), 256>>>(hop_v);
        wsum_kernel<<<dim3(64, 2), 256>>>(enc, 0);
        hred_kernel<<<dim3(4, 2), 256>>>(out, t);
        proj_kernel<<<dim3(4, 2), 256>>>(attn_wq, 1, p);
        attn_score_kernel<<<dim3(NN / 8, 2), 256>>>(attn_v);
        wsum_kernel<<<dim3(64, 1), 256>>>(enc, 1);
        actor_fin_kernel<<<1, 256>>>(enc, out, t);
        cred_kernel<<<1, 1024>>>(score_w, score_b, out, t);
    }
}

// round 3
// speedup vs baseline: 1.9449x; 1.9449x over previous
#include <cuda_runtime.h>
#include <cuda_bf16.h>
#include <math.h>
#include <stdint.h>

#define NN 8192
#define HH 1024
#define NSTEPS 8
#define KEXP 3072
#define BK 32
#define NKT (KEXP / BK)        // 96
#define STRIDE 40              // padded bf16 row stride in smem

// ---------------- persistent device state (no allocs allowed) ----------------
__device__ float g_attn_feat[NN * HH];
__device__ float g_hop_feat[NN * HH];
__device__ __nv_bfloat16 g_Aexp[(size_t)NN * KEXP];      // enc split-expanded: hi|lo|hi
__device__ __nv_bfloat16 g_Bexp[2][(size_t)HH * KEXP];   // wm^T split-expanded: hi|hi|lo
__device__ float g_hbuf[2][2][HH];
__device__ float g_cbuf[2][2][HH];
__device__ float g_x[2][HH];
__device__ float g_q[2][HH];
__device__ float g_hq[2][HH];
__device__ float g_aq[2][HH];
__device__ float g_sel[NN];
__device__ float g_neg[NN];
__device__ float g_w[2][NN];
__device__ float g_part[2][64][HH];
__device__ float g_amax_val[NN / 8];
__device__ int   g_amax_idx[NN / 8];

__device__ __forceinline__ float tanh_approx(float x) {
    float y;
    asm("tanh.approx.f32 %0, %1;" : "=f"(y) : "f"(x));
    return y;
}
__device__ __forceinline__ float sigmoidf_(float x) { return 1.0f / (1.0f + expf(-x)); }

__device__ __forceinline__ uint32_t s2u(const void* p) {
    uint32_t a;
    asm("{ .reg .u64 t; cvta.to.shared.u64 t, %1; cvt.u32.u64 %0, t; }" : "=r"(a) : "l"(p));
    return a;
}
__device__ __forceinline__ void cp_async16(uint32_t dst, const void* src) {
    asm volatile("cp.async.cg.shared.global [%0], [%1], 16;" :: "r"(dst), "l"(src));
}

// ---------------- init ----------------
__global__ void init_kernel(const int* __restrict__ mask, const float* __restrict__ init_i,
                            const float* __restrict__ init_h, const float* __restrict__ init_c) {
    int i = blockIdx.x * 256 + threadIdx.x;
    if (i < NN) {
        g_sel[i] = 0.0f;
        g_neg[i] = (mask[i] == 0) ? -1e8f : 0.0f;
    }
    if (i < HH) {
        g_x[0][i] = init_i[i];      g_x[1][i] = init_i[i];
        g_hbuf[0][0][i] = init_h[i]; g_hbuf[0][1][i] = init_h[i];
        g_cbuf[0][0][i] = init_c[i]; g_cbuf[0][1][i] = init_c[i];
    }
}

// ---------------- bf16 hi/lo expansion of enc: segments hi | lo | hi ----------------
__global__ void conv_enc_kernel(const float* __restrict__ enc) {
    size_t i = ((size_t)blockIdx.x * 256 + threadIdx.x) * 4;
    int m = (int)(i >> 10);
    int k = (int)(i & 1023);
    float4 x = *(const float4*)(enc + i);
    __nv_bfloat16 h0 = __float2bfloat16(x.x), h1 = __float2bfloat16(x.y);
    __nv_bfloat16 h2 = __float2bfloat16(x.z), h3 = __float2bfloat16(x.w);
    __nv_bfloat16 l0 = __float2bfloat16(x.x - __bfloat162float(h0));
    __nv_bfloat16 l1 = __float2bfloat16(x.y - __bfloat162float(h1));
    __nv_bfloat16 l2 = __float2bfloat16(x.z - __bfloat162float(h2));
    __nv_bfloat16 l3 = __float2bfloat16(x.w - __bfloat162float(h3));
    __nv_bfloat16* b = g_Aexp + (size_t)m * KEXP + k;
    __nv_bfloat162* p0 = (__nv_bfloat162*)(b);
    __nv_bfloat162* p1 = (__nv_bfloat162*)(b + 1024);
    __nv_bfloat162* p2 = (__nv_bfloat162*)(b + 2048);
    p0[0] = __nv_bfloat162(h0, h1); p0[1] = __nv_bfloat162(h2, h3);
    p1[0] = __nv_bfloat162(l0, l1); p1[1] = __nv_bfloat162(l2, l3);
    p2[0] = __nv_bfloat162(h0, h1); p2[1] = __nv_bfloat162(h2, h3);
}

// ---------------- transpose + expand weights: B[h][k'] = hi | hi | lo ----------------
__global__ void conv_w_kernel(const float* __restrict__ w0, const float* __restrict__ w1) {
    const float* W = blockIdx.z ? w1 : w0;
    __nv_bfloat16* out = g_Bexp[blockIdx.z];
    __shared__ float t[32][33];
    int k0 = blockIdx.y * 32, h0 = blockIdx.x * 32;
    for (int r = threadIdx.y; r < 32; r += 8)
        t[r][threadIdx.x] = W[(size_t)(k0 + r) * HH + h0 + threadIdx.x];
    __syncthreads();
    for (int r = threadIdx.y; r < 32; r += 8) {
        float x = t[threadIdx.x][r];  // = W[k0+tx][h0+r]
        __nv_bfloat16 hi = __float2bfloat16(x);
        __nv_bfloat16 lo = __float2bfloat16(x - __bfloat162float(hi));
        __nv_bfloat16* o = out + (size_t)(h0 + r) * KEXP + k0 + threadIdx.x;
        o[0] = hi; o[1024] = hi; o[2048] = lo;
    }
}

// ---------------- HMMA GEMM: C[m,h] = Aexp[m,:] . Bexp[h,:] ----------------
// CTA 128x128, BK=32, 256 thr, 8 warps (4m x 2n), warp tile 32x64.
__global__ void __launch_bounds__(256) mma_gemm_kernel() {
    __shared__ __nv_bfloat16 As[2][128 * STRIDE];
    __shared__ __nv_bfloat16 Bs[2][128 * STRIDE];

    const int tid = threadIdx.x;
    const int wid = tid >> 5, lane = tid & 31;
    const int wm = wid & 3, wn = wid >> 2;
    const int g = lane >> 2, tig = lane & 3;
    const int m0 = blockIdx.y * 128, n0 = blockIdx.x * 128;

    const __nv_bfloat16* Ab = g_Aexp + (size_t)m0 * KEXP;
    const __nv_bfloat16* Bb = g_Bexp[blockIdx.z] + (size_t)n0 * KEXP;

    // each thread copies 2 A-chunks + 2 B-chunks of 16B per stage
    const int c0 = tid * 2;                 // chunk ids c0, c0+1 of 512
    const int r0 = c0 >> 2, q0 = (c0 & 3) * 8;
    const int r1 = (c0 + 1) >> 2, q1 = ((c0 + 1) & 3) * 8;

    float acc[2][8][4];
#pragma unroll
    for (int i = 0; i < 2; i++)
#pragma unroll
        for (int j = 0; j < 8; j++)
#pragma unroll
            for (int v = 0; v < 4; v++) acc[i][j][v] = 0.0f;

    uint32_t asb[2], bsb[2];
#pragma unroll
    for (int s = 0; s < 2; s++) { asb[s] = s2u(As[s]); bsb[s] = s2u(Bs[s]); }

    // prologue: stage 0
    cp_async16(asb[0] + (r0 * STRIDE + q0) * 2, Ab + (size_t)r0 * KEXP + q0);
    cp_async16(asb[0] + (r1 * STRIDE + q1) * 2, Ab + (size_t)r1 * KEXP + q1);
    cp_async16(bsb[0] + (r0 * STRIDE + q0) * 2, Bb + (size_t)r0 * KEXP + q0);
    cp_async16(bsb[0] + (r1 * STRIDE + q1) * 2, Bb + (size_t)r1 * KEXP + q1);
    asm volatile("cp.async.commit_group;");

    for (int kt = 0; kt < NKT; kt++) {
        const int cur = kt & 1;
        if (kt + 1 < NKT) {
            const int nxt = cur ^ 1;
            const size_t k0 = (size_t)(kt + 1) * BK;
            cp_async16(asb[nxt] + (r0 * STRIDE + q0) * 2, Ab + (size_t)r0 * KEXP + k0 + q0);
            cp_async16(asb[nxt] + (r1 * STRIDE + q1) * 2, Ab + (size_t)r1 * KEXP + k0 + q1);
            cp_async16(bsb[nxt] + (r0 * STRIDE + q0) * 2, Bb + (size_t)r0 * KEXP + k0 + q0);
            cp_async16(bsb[nxt] + (r1 * STRIDE + q1) * 2, Bb + (size_t)r1 * KEXP + k0 + q1);
            asm volatile("cp.async.commit_group;");
            asm volatile("cp.async.wait_group 1;");
        } else {
            asm volatile("cp.async.wait_group 0;");
        }
        __syncthreads();

        const __nv_bfloat16* Asl = As[cur];
        const __nv_bfloat16* Bsl = Bs[cur];
#pragma unroll
        for (int ks = 0; ks < 2; ks++) {
            const int ko = ks * 16;
            uint32_t a[2][4], b[8][2];
#pragma unroll
            for (int mt = 0; mt < 2; mt++) {
                const int row = wm * 32 + mt * 16 + g;
                const __nv_bfloat16* p = Asl + row * STRIDE + ko + tig * 2;
                a[mt][0] = *(const uint32_t*)(p);
                a[mt][1] = *(const uint32_t*)(p + 8 * STRIDE);
                a[mt][2] = *(const uint32_t*)(p + 8);
                a[mt][3] = *(const uint32_t*)(p + 8 * STRIDE + 8);
            }
#pragma unroll
            for (int nt = 0; nt < 8; nt++) {
                const int row = wn * 64 + nt * 8 + g;
                const __nv_bfloat16* p = Bsl + row * STRIDE + ko + tig * 2;
                b[nt][0] = *(const uint32_t*)(p);
                b[nt][1] = *(const uint32_t*)(p + 8);
            }
#pragma unroll
            for (int mt = 0; mt < 2; mt++)
#pragma unroll
                for (int nt = 0; nt < 8; nt++) {
                    asm volatile(
                        "mma.sync.aligned.m16n8k16.row.col.f32.bf16.bf16.f32 "
                        "{%0,%1,%2,%3}, {%4,%5,%6,%7}, {%8,%9}, {%0,%1,%2,%3};"
                        : "+f"(acc[mt][nt][0]), "+f"(acc[mt][nt][1]),
                          "+f"(acc[mt][nt][2]), "+f"(acc[mt][nt][3])
                        : "r"(a[mt][0]), "r"(a[mt][1]), "r"(a[mt][2]), "r"(a[mt][3]),
                          "r"(b[nt][0]), "r"(b[nt][1]));
                }
        }
        __syncthreads();
    }

    float* C = blockIdx.z ? g_hop_feat : g_attn_feat;
#pragma unroll
    for (int mt = 0; mt < 2; mt++) {
        const int rbase = m0 + wm * 32 + mt * 16 + g;
#pragma unroll
        for (int nt = 0; nt < 8; nt++) {
            const int col = n0 + wn * 64 + nt * 8 + tig * 2;
            *(float2*)&C[(size_t)rbase * HH + col] = make_float2(acc[mt][nt][0], acc[mt][nt][1]);
            *(float2*)&C[(size_t)(rbase + 8) * HH + col] = make_float2(acc[mt][nt][2], acc[mt][nt][3]);
        }
    }
}

// ---------------- LSTM step (both chains; also zeroes g_hq for proj atomics) ------
__global__ void lstm_kernel(const float* __restrict__ w_ih, const float* __restrict__ w_hh,
                            const float* __restrict__ b_ih, const float* __restrict__ b_hh,
                            int parity) {
    const int chain = blockIdx.y;
    __shared__ float xs[HH], hs[HH];
    for (int i = threadIdx.x; i < HH; i += 256) {
        xs[i] = g_x[chain][i];
        hs[i] = g_hbuf[parity][chain][i];
    }
    __syncthreads();
    const int warp = threadIdx.x >> 5, lane = threadIdx.x & 31;
    const int j = blockIdx.x * 8 + warp;
    float acc[4];
#pragma unroll
    for (int g = 0; g < 4; g++) {
        const float* wi = w_ih + (size_t)(g * HH + j) * HH;
        const float* wh = w_hh + (size_t)(g * HH + j) * HH;
        float a = 0.0f;
        for (int k = lane; k < HH; k += 32) a += xs[k] * wi[k] + hs[k] * wh[k];
        acc[g] = a;
    }
#pragma unroll
    for (int o = 16; o; o >>= 1)
#pragma unroll
        for (int g = 0; g < 4; g++) acc[g] += __shfl_xor_sync(0xffffffffu, acc[g], o);
    if (lane == 0) {
        float gi = sigmoidf_(acc[0] + b_ih[j] + b_hh[j]);
        float gf = sigmoidf_(acc[1] + b_ih[HH + j] + b_hh[HH + j]);
        float gg = tanhf(acc[2] + b_ih[2 * HH + j] + b_hh[2 * HH + j]);
        float go = sigmoidf_(acc[3] + b_ih[3 * HH + j] + b_hh[3 * HH + j]);
        float cn = gf * g_cbuf[parity][chain][j] + gi * gg;
        g_cbuf[parity ^ 1][chain][j] = cn;
        g_hbuf[parity ^ 1][chain][j] = go * tanhf(cn);
        g_hq[chain][j] = 0.0f;   // cleared for proj's atomic accumulation
    }
}

// ---------------- query projection (k-split + atomic accumulate) ----------------
__global__ void proj_kernel(const float* __restrict__ W, int mode, int parity) {
    const int chain = blockIdx.z;
    const float* v = (mode == 0) ? g_hbuf[parity ^ 1][chain] : g_q[chain];
    float* o = (mode == 0) ? g_hq[chain] : g_aq[chain];
    __shared__ float vs[64];
    const int k0 = blockIdx.y * 64;
    if (threadIdx.x < 64) vs[threadIdx.x] = v[k0 + threadIdx.x];
    __syncthreads();
    const int col = blockIdx.x * 256 + threadIdx.x;
    float acc = 0.0f;
#pragma unroll
    for (int k = 0; k < 64; k++) acc += vs[k] * W[(size_t)(k0 + k) * HH + col];
    atomicAdd(&o[col], acc);
}

// ---------------- glimpse scores -> softmax weights (both chains) ----------------
__global__ void hop_score_kernel(const float* __restrict__ hop_v) {
    const int chain = blockIdx.y;
    __shared__ float qs[HH], vs[HH];
    for (int i = threadIdx.x; i < HH; i += 256) { qs[i] = g_hq[chain][i]; vs[i] = hop_v[i]; }
    __syncthreads();
    const int warp = threadIdx.x >> 5, lane = threadIdx.x & 31;
    const int n = blockIdx.x * 8 + warp;
    const float4* row = (const float4*)&g_hop_feat[(size_t)n * HH];
    float acc = 0.0f;
#pragma unroll
    for (int it = 0; it < 8; it++) {
        int k4 = lane + it * 32, k = k4 * 4;
        float4 f = row[k4];
        acc += tanh_approx(f.x + qs[k]) * vs[k] + tanh_approx(f.y + qs[k + 1]) * vs[k + 1]
             + tanh_approx(f.z + qs[k + 2]) * vs[k + 2] + tanh_approx(f.w + qs[k + 3]) * vs[k + 3];
    }
#pragma unroll
    for (int o = 16; o; o >>= 1) acc += __shfl_xor_sync(0xffffffffu, acc, o);
    if (lane == 0) g_w[chain][n] = expf(acc + g_neg[n]);
}

// ---------------- hop weighted-sum partials, both chains in one feat pass --------
__global__ void wsum_hop_kernel() {
    const int c = threadIdx.x * 4;
    const int n0 = blockIdx.x * (NN / 64);
    float a00 = 0, a01 = 0, a02 = 0, a03 = 0;
    float a10 = 0, a11 = 0, a12 = 0, a13 = 0;
#pragma unroll 4
    for (int n = n0; n < n0 + NN / 64; n++) {
        float w0 = g_w[0][n], w1 = g_w[1][n];
        float4 f = *(const float4*)&g_hop_feat[(size_t)n * HH + c];
        a00 += w0 * f.x; a01 += w0 * f.y; a02 += w0 * f.z; a03 += w0 * f.w;
        a10 += w1 * f.x; a11 += w1 * f.y; a12 += w1 * f.z; a13 += w1 * f.w;
    }
    *(float4*)&g_part[0][blockIdx.x][c] = make_float4(a00, a01, a02, a03);
    *(float4*)&g_part[1][blockIdx.x][c] = make_float4(a10, a11, a12, a13);
}

// ---------------- critic ctx weighted-sum over enc ----------------
__global__ void wsum_enc_kernel(const float* __restrict__ enc) {
    const float* w = g_w[1];
    const int c = threadIdx.x * 4;
    const int n0 = blockIdx.x * (NN / 64);
    float a0 = 0, a1 = 0, a2 = 0, a3 = 0;
#pragma unroll 4
    for (int n = n0; n < n0 + NN / 64; n++) {
        float wn = w[n];
        float4 f = *(const float4*)&enc[(size_t)n * HH + c];
        a0 += wn * f.x; a1 += wn * f.y; a2 += wn * f.z; a3 += wn * f.w;
    }
    *(float4*)&g_part[1][blockIdx.x][c] = make_float4(a0, a1, a2, a3);
}

// ---------------- reduce partials -> q; also zeroes g_aq; actor writes states ----
__global__ void hred_kernel(float* __restrict__ out, int step) {
    const int chain = blockIdx.y;
    const int col = blockIdx.x * 256 + threadIdx.x;
    float s = 0.0f;
#pragma unroll
    for (int b = 0; b < 64; b++) s += g_part[chain][b][col];
    float sw = 0.0f;
    for (int i = threadIdx.x; i < NN; i += 256) sw += g_w[chain][i];
#pragma unroll
    for (int o = 16; o; o >>= 1) sw += __shfl_xor_sync(0xffffffffu, sw, o);
    __shared__ float red[8];
    if ((threadIdx.x & 31) == 0) red[threadIdx.x >> 5] = sw;
    __syncthreads();
    float tot = 0.0f;
#pragma unroll
    for (int w = 0; w < 8; w++) tot += red[w];
    float q = s / tot;
    g_q[chain][col] = q;
    g_aq[chain][col] = 0.0f;   // cleared for proj's atomic accumulation
    if (chain == 0) out[NSTEPS + step * HH + col] = q;
}

// ---------------- attn scores: actor -> argmax partials, critic -> weights ----------
__global__ void attn_score_kernel(const float* __restrict__ attn_v) {
    const int chain = blockIdx.y;
    __shared__ float qs[HH], vs[HH];
    __shared__ float sv[8]; __shared__ int si[8];
    for (int i = threadIdx.x; i < HH; i += 256) { qs[i] = g_aq[chain][i]; vs[i] = attn_v[i]; }
    __syncthreads();
    const int warp = threadIdx.x >> 5, lane = threadIdx.x & 31;
    const int n = blockIdx.x * 8 + warp;
    const float4* row = (const float4*)&g_attn_feat[(size_t)n * HH];
    float acc = 0.0f;
#pragma unroll
    for (int it = 0; it < 8; it++) {
        int k4 = lane + it * 32, k = k4 * 4;
        float4 f = row[k4];
        acc += tanh_approx(f.x + qs[k]) * vs[k] + tanh_approx(f.y + qs[k + 1]) * vs[k + 1]
             + tanh_approx(f.z + qs[k + 2]) * vs[k + 2] + tanh_approx(f.w + qs[k + 3]) * vs[k + 3];
    }
#pragma unroll
    for (int o = 16; o; o >>= 1) acc += __shfl_xor_sync(0xffffffffu, acc, o);
    if (chain == 0) {
        if (lane == 0) { sv[warp] = acc + g_neg[n] + g_sel[n]; si[warp] = n; }
        __syncthreads();
        if (threadIdx.x == 0) {
            float bv = sv[0]; int bi = si[0];
#pragma unroll
            for (int w = 1; w < 8; w++)
                if (sv[w] > bv) { bv = sv[w]; bi = si[w]; }
            g_amax_val[blockIdx.x] = bv; g_amax_idx[blockIdx.x] = bi;
        }
    } else {
        if (lane == 0) g_w[1][n] = expf(acc + g_neg[n]);
    }
}

// ---------------- actor finalize ----------------
__global__ void actor_fin_kernel(const float* __restrict__ enc, float* __restrict__ out, int step) {
    __shared__ float bv[256]; __shared__ int bi[256];
    const int tid = threadIdx.x;
    float v = -3.4e38f; int id = 0;
    for (int b = tid; b < NN / 8; b += 256) {
        float pv = g_amax_val[b]; int pi = g_amax_idx[b];
        if (pv > v || (pv == v && pi < id)) { v = pv; id = pi; }
    }
    bv[tid] = v; bi[tid] = id;
    __syncthreads();
    for (int s = 128; s > 0; s >>= 1) {
        if (tid < s) {
            if (bv[tid + s] > bv[tid] || (bv[tid + s] == bv[tid] && bi[tid + s] < bi[tid])) {
                bv[tid] = bv[tid + s]; bi[tid] = bi[tid + s];
            }
        }
        __syncthreads();
    }
    __shared__ int chosen;
    if (tid == 0) {
        chosen = bi[0];
        g_sel[bi[0]] = -1e18f;
        out[step] = (float)bi[0];
    }
    __syncthreads();
    const int idx = chosen;
    for (int i = tid; i < HH; i += 256) g_x[0][i] = enc[(size_t)idx * HH + i];
}

// ---------------- critic reduce ----------------
__global__ void cred_kernel(const float* __restrict__ score_w, const float* __restrict__ score_b,
                            float* __restrict__ out, int step) {
    const int col = threadIdx.x;
    float s = 0.0f;
#pragma unroll
    for (int b = 0; b < 64; b++) s += g_part[1][b][col];
    float sw = 0.0f;
    for (int i = col; i < NN; i += 1024) sw += g_w[1][i];
#pragma unroll
    for (int o = 16; o; o >>= 1) sw += __shfl_xor_sync(0xffffffffu, sw, o);
    __shared__ float red[32];
    if ((col & 31) == 0) red[col >> 5] = sw;
    __syncthreads();
    float tot = 0.0f;
#pragma unroll
    for (int w = 0; w < 32; w++) tot += red[w];
    float ctx = s / tot;
    g_x[1][col] = ctx;
    float t = ctx * score_w[col];
#pragma unroll
    for (int o = 16; o; o >>= 1) t += __shfl_xor_sync(0xffffffffu, t, o);
    __shared__ float red2[32];
    if ((col & 31) == 0) red2[col >> 5] = t;
    __syncthreads();
    if (col == 0) {
        float stot = 0.0f;
#pragma unroll
        for (int w = 0; w < 32; w++) stot += red2[w];
        out[NSTEPS + NSTEPS * HH + step] = stot + score_b[0];
    }
}

// ---------------- launch ----------------
extern "C" void kernel_launch(void* const* d_in, const int* in_sizes, int n_in,
                              void* d_out, int out_size) {
    const float* enc     = (const float*)d_in[0];
    const int*   mask    = (const int*)d_in[1];
    const float* attn_wm = (const float*)d_in[2];
    const float* attn_wq = (const float*)d_in[3];
    const float* attn_v  = (const float*)d_in[4];
    const float* hop_wm  = (const float*)d_in[5];
    const float* hop_wq  = (const float*)d_in[6];
    const float* hop_v   = (const float*)d_in[7];
    const float* init_i  = (const float*)d_in[8];
    const float* init_h  = (const float*)d_in[9];
    const float* init_c  = (const float*)d_in[10];
    const float* w_ih    = (const float*)d_in[11];
    const float* w_hh    = (const float*)d_in[12];
    const float* b_ih    = (const float*)d_in[13];
    const float* b_hh    = (const float*)d_in[14];
    const float* score_w = (const float*)d_in[15];
    const float* score_b = (const float*)d_in[16];
    float* out = (float*)d_out;

    init_kernel<<<32, 256>>>(mask, init_i, init_h, init_c);
    conv_enc_kernel<<<NN * HH / 1024, 256>>>(enc);
    conv_w_kernel<<<dim3(32, 32, 2), dim3(32, 8)>>>(attn_wm, hop_wm);
    mma_gemm_kernel<<<dim3(8, 64, 2), 256>>>();

    for (int t = 0; t < NSTEPS; t++) {
        const int p = t & 1;
        lstm_kernel<<<dim3(128, 2), 256>>>(w_ih, w_hh, b_ih, b_hh, p);
        proj_kernel<<<dim3(4, 16, 2), 256>>>(hop_wq, 0, p);
        hop_score_kernel<<<dim3(NN / 8, 2), 256>>>(hop_v);
        wsum_hop_kernel<<<64, 256>>>();
        hred_kernel<<<dim3(4, 2), 256>>>(out, t);
        proj_kernel<<<dim3(4, 16, 2), 256>>>(attn_wq, 1, p);
        attn_score_kernel<<<dim3(NN / 8, 2), 256>>>(attn_v);
        wsum_enc_kernel<<<64, 256>>>(enc);
        actor_fin_kernel<<<1, 256>>>(enc, out, t);
        cred_kernel<<<1, 1024>>>(score_w, score_b, out, t);
    }
}